// round 15
// baseline (speedup 1.0000x reference)
#include <cuda_runtime.h>
#include <cstdint>

// BestChangeLayer: B batches, 25x25 binary grids, 512 candidate 3x3 patterns,
// one Conway step on a 7x7 window, L1 error on inner 5x5 vs target,
// argmin(err + 0.5*noise), write winning pattern into x at (ry, rx).
//
// Bitboards: 7x7 packed in u64 at bit (r*8 + c).
// 128 threads/block, TWO batches per block (one latency exposure covers two
// batches of compute), 4 patterns per thread per batch: p = 4*tid + j;
// j toggles board bits 35/36. Shared CSA per batch; variants ripple-add
// constant neighbor masks. launch_bounds(128,4): occupancy is grid-limited
// (512 blocks), so no reg cap -> no spills.

#define NPAT 512
typedef unsigned long long u64;

#define REDOR64(v) ( ((u64)__reduce_or_sync(0xffffffffu,(unsigned)((v) >> 32)) << 32) \
                   |  (u64)__reduce_or_sync(0xffffffffu,(unsigned)(v)) )

__global__ __launch_bounds__(128, 4)
void bcl_kernel(const float* __restrict__ x,
                const float* __restrict__ target,
                const float* __restrict__ noise,
                const int* __restrict__ ryp,
                const int* __restrict__ rxp,
                float* __restrict__ out,
                int B)
{
    __shared__ u64 s_fixed[2];   // per-batch 7x7 influence, center cleared
    __shared__ u64 s_targ[2];    // per-batch 5x5 target at rows/cols 1..5
    __shared__ u64 sk[2][4];     // per-batch per-warp best key

    const int tid  = threadIdx.x;
    const int warp = tid >> 5;
    const int lane = tid & 31;

    const int bA = blockIdx.x * 2;
    int bB = bA + 1; if (bB >= B) bB = B - 1;   // odd-B: benign duplicate

    const float* __restrict__ xbA = x + bA * 625;
    const float* __restrict__ xbB = x + bB * 625;
    float* __restrict__ obA = out + bA * 625;
    float* __restrict__ obB = out + bB * 625;

    const int ry = *ryp, rx = *rxp;

    // ---- Critical-path gathers first (warp-specialized, scattered LDGs).
    //      Periodic indexing via conditional subtracts (args stay < 54). ----
    if (warp < 2) {
        // 7x7 influence window (center 3x3 cleared): batch A (w0) / B (w1).
        const float* __restrict__ src = warp ? xbB : xbA;
        u64 pf = 0;
        #pragma unroll
        for (int it = 0; it < 2; it++) {
            int item = lane + it * 32;
            if (item < 49) {
                int r = item / 7, c = item % 7;
                if (!(r >= 2 && r <= 4 && c >= 2 && c <= 4)) {
                    int rr = ry + 23 + r; if (rr >= 25) rr -= 25; if (rr >= 25) rr -= 25;
                    int cc = rx + 23 + c; if (cc >= 25) cc -= 25; if (cc >= 25) cc -= 25;
                    if (src[rr * 25 + cc] != 0.0f) pf |= 1ULL << (r * 8 + c);
                }
            }
        }
        u64 f = REDOR64(pf);
        if (lane == 0) s_fixed[warp] = f;
    } else {
        // 5x5 target window: batch A (w2) / B (w3).
        const float* __restrict__ src = target + (warp == 2 ? bA : bB) * 625;
        u64 pt = 0;
        if (lane < 25) {
            int r = lane / 5, c = lane % 5;
            int rr = ry + 24 + r; if (rr >= 25) rr -= 25; if (rr >= 25) rr -= 25;
            int cc = rx + 24 + c; if (cc >= 25) cc -= 25; if (cc >= 25) cc -= 25;
            if (src[rr * 25 + cc] != 0.0f) pt |= 1ULL << ((r + 1) * 8 + (c + 1));
        }
        u64 tg = REDOR64(pt);
        if (lane == 0) s_targ[warp - 2] = tg;
    }

    // ---- Non-critical loads (noise + copy), then copy stores ----
    const float4 nzA = ((const float4*)noise)[bA * 128 + tid];
    const float4 nzB = ((const float4*)noise)[bB * 128 + tid];

    float xa0 = xbA[tid],       xa1 = xbA[tid + 128];
    float xa2 = xbA[tid + 256], xa3 = xbA[tid + 384];
    float xa4 = (tid < 113) ? xbA[tid + 512] : 0.0f;
    float xc0 = xbB[tid],       xc1 = xbB[tid + 128];
    float xc2 = xbB[tid + 256], xc3 = xbB[tid + 384];
    float xc4 = (tid < 113) ? xbB[tid + 512] : 0.0f;

    obA[tid]       = xa0;  obA[tid + 128] = xa1;
    obA[tid + 256] = xa2;  obA[tid + 384] = xa3;
    if (tid < 113) obA[tid + 512] = xa4;
    obB[tid]       = xc0;  obB[tid + 128] = xc1;
    obB[tid + 256] = xc2;  obB[tid + 384] = xc3;
    if (tid < 113) obB[tid + 512] = xc4;

    // Base pattern mask: p = 4*tid + j; element k (r=k/3,c=k%3) = (p>>(8-k))&1
    // at board bit (2+r)*8+(2+c).  tid bits 6..0 -> board bits
    // 18,19,20 (row0, reversed triple), 26,27,28 (row1, reversed), 34.
    const u64 base = ((u64)(__brev((tid >> 4) & 7) >> 29) << 18)
                   | ((u64)(__brev((tid >> 1) & 7) >> 29) << 26)
                   | ((u64)(tid & 1) << 34);

    __syncthreads();

    const u64 M    = 0x007F7F7F7F7F7F7FULL;     // col-shift guard
    const u64 CROP = 0x00003E3E3E3E3E00ULL;     // rows 1..5, cols 1..5
    const u64 B35  = 1ULL << 35, B36 = 1ULL << 36;
    // Constant neighbor masks of center cells (4,3) and (4,4):
    const u64 M35 = 0x00001C141C000000ULL;
    const u64 M36 = 0x0000382838000000ULL;

    const u64 fxA = s_fixed[0], fxB = s_fixed[1];
    const u64 tgA = s_targ[0],  tgB = s_targ[1];

    u64 bestA = ~0ULL, bestB = ~0ULL;

#define FIN(NEXT, TG, P, NZS, BEST)                                          \
    {                                                                        \
        int err = __popcll(((NEXT) & CROP) ^ (TG));                          \
        float sd = (float)err + (NZS) * 0.5f;                                \
        u64 key = ((u64)__float_as_uint(sd) << 32) | (unsigned)(P);          \
        if (key < (BEST)) (BEST) = key;                                      \
    }

    // One CSA over the 8 neighbor planes of Bc -> bit-sliced count
    // (cc0 = count bit0, cc1 = parity of weight-2 sum, hi = sum>=2);
    // alive: cc1 & ~hi & (cc0 | cell). Variants j add center bits 36/35 by
    // ripple-adding their constant neighbor masks (exact).
#define EVAL_BATCH(FIXED, TG, NZ, BEST)                                      \
    {                                                                        \
        const u64 Bc = (FIXED) | base;                                       \
        u64 n1 = (Bc << 1) & M, n2 = (Bc >> 1) & M;                          \
        u64 n3 = Bc << 8, n4 = Bc >> 8;                                      \
        u64 n5 = n1 << 8, n6 = n1 >> 8, n7 = n2 << 8, n8 = n2 >> 8;          \
        u64 a1 = n1 ^ n2, b1 = n1 & n2;                                      \
        u64 a2 = n3 ^ n4, b2 = n3 & n4;                                      \
        u64 a3 = n5 ^ n6, b3 = n5 & n6;                                      \
        u64 a4 = n7 ^ n8, b4 = n7 & n8;                                      \
        u64 s1 = a1 ^ a2, t1 = a1 & a2;                                      \
        u64 s2 = a3 ^ a4, t2 = a3 & a4;                                      \
        u64 cc0 = s1 ^ s2, u0 = s1 & s2;                                     \
        u64 p1 = b1 ^ b2, q1 = b1 & b2;                                      \
        u64 p2 = b3 ^ b4, q2 = b3 & b4;                                      \
        u64 p3 = t1 ^ t2, q3 = t1 & t2;                                      \
        u64 r1 = p1 ^ p2, w1 = p1 & p2;                                      \
        u64 r2 = p3 ^ u0, w2 = p3 & u0;                                      \
        u64 cc1 = r1 ^ r2, w3 = r1 & r2;                                     \
        u64 hi = q1 | q2 | q3 | w1 | w2 | w3;                                \
        { /* j=0: no toggles */                                              \
            u64 nx = cc1 & ~hi & (cc0 | Bc);                                 \
            FIN(nx, TG, 4 * tid + 0, (NZ).x, BEST)                           \
        }                                                                    \
        { /* j=1: +bit36 */                                                  \
            u64 k0 = cc0 & M36, a0v = cc0 ^ M36;                             \
            u64 av = cc1 ^ k0, h = hi | (cc1 & k0);                          \
            u64 nx = av & ~h & (a0v | Bc | B36);                             \
            FIN(nx, TG, 4 * tid + 1, (NZ).y, BEST)                           \
        }                                                                    \
        { /* j=2: +bit35 */                                                  \
            u64 k0 = cc0 & M35, a0v = cc0 ^ M35;                             \
            u64 av = cc1 ^ k0, h = hi | (cc1 & k0);                          \
            u64 nx = av & ~h & (a0v | Bc | B35);                             \
            FIN(nx, TG, 4 * tid + 2, (NZ).z, BEST)                           \
        }                                                                    \
        { /* j=3: +bit35 then +bit36 (sequential ripple, exact) */           \
            u64 k0 = cc0 & M35, a0v = cc0 ^ M35;                             \
            u64 av = cc1 ^ k0, h1 = hi | (cc1 & k0);                         \
            u64 k1 = a0v & M36, g0 = a0v ^ M36;                              \
            u64 gv = av ^ k1, h2 = h1 | (av & k1);                           \
            u64 nx = gv & ~h2 & (g0 | Bc | B35 | B36);                       \
            FIN(nx, TG, 4 * tid + 3, (NZ).w, BEST)                           \
        }                                                                    \
    }

    EVAL_BATCH(fxA, tgA, nzA, bestA)
    EVAL_BATCH(fxB, tgB, nzB, bestB)
#undef EVAL_BATCH
#undef FIN

    // Warp argmin for both batches (packed keys, first-index tiebreak).
    #pragma unroll
    for (int s = 16; s; s >>= 1) {
        u64 oa = __shfl_xor_sync(0xffffffffu, bestA, s);
        u64 ob = __shfl_xor_sync(0xffffffffu, bestB, s);
        if (oa < bestA) bestA = oa;
        if (ob < bestB) bestB = ob;
    }
    if (lane == 0) { sk[0][warp] = bestA; sk[1][warp] = bestB; }

    __syncthreads();   // publishes sk; orders copy stores before patch

    if (tid < 9) {
        u64 k0 = sk[0][0];
        if (sk[0][1] < k0) k0 = sk[0][1];
        if (sk[0][2] < k0) k0 = sk[0][2];
        if (sk[0][3] < k0) k0 = sk[0][3];
        int best = (int)(unsigned)k0;
        float vv = ((best >> (8 - tid)) & 1) ? 1.0f : 0.0f;
        obA[(ry + tid / 3) * 25 + (rx + tid % 3)] = vv;
    } else if (warp == 1 && lane < 9) {
        u64 k0 = sk[1][0];
        if (sk[1][1] < k0) k0 = sk[1][1];
        if (sk[1][2] < k0) k0 = sk[1][2];
        if (sk[1][3] < k0) k0 = sk[1][3];
        int best = (int)(unsigned)k0;
        float vv = ((best >> (8 - lane)) & 1) ? 1.0f : 0.0f;
        obB[(ry + lane / 3) * 25 + (rx + lane % 3)] = vv;
    }
}

extern "C" void kernel_launch(void* const* d_in, const int* in_sizes, int n_in,
                              void* d_out, int out_size)
{
    const float* x      = (const float*)d_in[0];
    const float* target = (const float*)d_in[1];
    const float* noise  = (const float*)d_in[2];
    const int*   ryp    = (const int*)d_in[3];
    const int*   rxp    = (const int*)d_in[4];
    float* out = (float*)d_out;

    int B = in_sizes[0] / 625;
    bcl_kernel<<<(B + 1) / 2, 128>>>(x, target, noise, ryp, rxp, out, B);
}

// round 16
// speedup vs baseline: 1.0706x; 1.0706x over previous
#include <cuda_runtime.h>
#include <cstdint>

// BestChangeLayer: B batches, 25x25 binary grids, 512 candidate 3x3 patterns,
// one Conway step on a 7x7 window, L1 error on inner 5x5 vs target,
// argmin(err + 0.5*noise), write winning pattern into x at (ry, rx).
//
// Bitboards: 7x7 packed in u64 at bit (r*8 + c).
// 128 threads/block, TWO batches per block (one latency exposure covers two
// batches of compute), 4 patterns per thread per batch: p = 4*tid + j;
// j toggles board bits 35/36. Shared CSA per batch; variants ripple-add
// constant neighbor masks. launch_bounds(128,4): occupancy is grid-limited
// (512 blocks), so no reg cap -> no spills.

#define NPAT 512
typedef unsigned long long u64;

#define REDOR64(v) ( ((u64)__reduce_or_sync(0xffffffffu,(unsigned)((v) >> 32)) << 32) \
                   |  (u64)__reduce_or_sync(0xffffffffu,(unsigned)(v)) )

__global__ __launch_bounds__(128, 4)
void bcl_kernel(const float* __restrict__ x,
                const float* __restrict__ target,
                const float* __restrict__ noise,
                const int* __restrict__ ryp,
                const int* __restrict__ rxp,
                float* __restrict__ out,
                int B)
{
    __shared__ u64 s_fixed[2];   // per-batch 7x7 influence, center cleared
    __shared__ u64 s_targ[2];    // per-batch 5x5 target at rows/cols 1..5
    __shared__ u64 sk[2][4];     // per-batch per-warp best key

    const int tid  = threadIdx.x;
    const int warp = tid >> 5;
    const int lane = tid & 31;

    const int bA = blockIdx.x * 2;
    int bB = bA + 1; if (bB >= B) bB = B - 1;   // odd-B: benign duplicate

    const float* __restrict__ xbA = x + bA * 625;
    const float* __restrict__ xbB = x + bB * 625;
    float* __restrict__ obA = out + bA * 625;
    float* __restrict__ obB = out + bB * 625;

    const int ry = *ryp, rx = *rxp;

    // ---- Critical-path gathers first (warp-specialized, scattered LDGs).
    //      Periodic indexing via conditional subtracts (args stay < 54). ----
    if (warp < 2) {
        // 7x7 influence window (center 3x3 cleared): batch A (w0) / B (w1).
        const float* __restrict__ src = warp ? xbB : xbA;
        u64 pf = 0;
        #pragma unroll
        for (int it = 0; it < 2; it++) {
            int item = lane + it * 32;
            if (item < 49) {
                int r = item / 7, c = item % 7;
                if (!(r >= 2 && r <= 4 && c >= 2 && c <= 4)) {
                    int rr = ry + 23 + r; if (rr >= 25) rr -= 25; if (rr >= 25) rr -= 25;
                    int cc = rx + 23 + c; if (cc >= 25) cc -= 25; if (cc >= 25) cc -= 25;
                    if (src[rr * 25 + cc] != 0.0f) pf |= 1ULL << (r * 8 + c);
                }
            }
        }
        u64 f = REDOR64(pf);
        if (lane == 0) s_fixed[warp] = f;
    } else {
        // 5x5 target window: batch A (w2) / B (w3).
        const float* __restrict__ src = target + (warp == 2 ? bA : bB) * 625;
        u64 pt = 0;
        if (lane < 25) {
            int r = lane / 5, c = lane % 5;
            int rr = ry + 24 + r; if (rr >= 25) rr -= 25; if (rr >= 25) rr -= 25;
            int cc = rx + 24 + c; if (cc >= 25) cc -= 25; if (cc >= 25) cc -= 25;
            if (src[rr * 25 + cc] != 0.0f) pt |= 1ULL << ((r + 1) * 8 + (c + 1));
        }
        u64 tg = REDOR64(pt);
        if (lane == 0) s_targ[warp - 2] = tg;
    }

    // ---- Non-critical loads (noise + copy), then copy stores ----
    const float4 nzA = ((const float4*)noise)[bA * 128 + tid];
    const float4 nzB = ((const float4*)noise)[bB * 128 + tid];

    float xa0 = xbA[tid],       xa1 = xbA[tid + 128];
    float xa2 = xbA[tid + 256], xa3 = xbA[tid + 384];
    float xa4 = (tid < 113) ? xbA[tid + 512] : 0.0f;
    float xc0 = xbB[tid],       xc1 = xbB[tid + 128];
    float xc2 = xbB[tid + 256], xc3 = xbB[tid + 384];
    float xc4 = (tid < 113) ? xbB[tid + 512] : 0.0f;

    obA[tid]       = xa0;  obA[tid + 128] = xa1;
    obA[tid + 256] = xa2;  obA[tid + 384] = xa3;
    if (tid < 113) obA[tid + 512] = xa4;
    obB[tid]       = xc0;  obB[tid + 128] = xc1;
    obB[tid + 256] = xc2;  obB[tid + 384] = xc3;
    if (tid < 113) obB[tid + 512] = xc4;

    // Base pattern mask: p = 4*tid + j; element k (r=k/3,c=k%3) = (p>>(8-k))&1
    // at board bit (2+r)*8+(2+c).  tid bits 6..0 -> board bits
    // 18,19,20 (row0, reversed triple), 26,27,28 (row1, reversed), 34.
    const u64 base = ((u64)(__brev((tid >> 4) & 7) >> 29) << 18)
                   | ((u64)(__brev((tid >> 1) & 7) >> 29) << 26)
                   | ((u64)(tid & 1) << 34);

    __syncthreads();

    const u64 M    = 0x007F7F7F7F7F7F7FULL;     // col-shift guard
    const u64 CROP = 0x00003E3E3E3E3E00ULL;     // rows 1..5, cols 1..5
    const u64 B35  = 1ULL << 35, B36 = 1ULL << 36;
    // Constant neighbor masks of center cells (4,3) and (4,4):
    const u64 M35 = 0x00001C141C000000ULL;
    const u64 M36 = 0x0000382838000000ULL;

    const u64 fxA = s_fixed[0], fxB = s_fixed[1];
    const u64 tgA = s_targ[0],  tgB = s_targ[1];

    u64 bestA = ~0ULL, bestB = ~0ULL;

#define FIN(NEXT, TG, P, NZS, BEST)                                          \
    {                                                                        \
        int err = __popcll(((NEXT) & CROP) ^ (TG));                          \
        float sd = (float)err + (NZS) * 0.5f;                                \
        u64 key = ((u64)__float_as_uint(sd) << 32) | (unsigned)(P);          \
        if (key < (BEST)) (BEST) = key;                                      \
    }

    // One CSA over the 8 neighbor planes of Bc -> bit-sliced count
    // (cc0 = count bit0, cc1 = parity of weight-2 sum, hi = sum>=2);
    // alive: cc1 & ~hi & (cc0 | cell). Variants j add center bits 36/35 by
    // ripple-adding their constant neighbor masks (exact).
#define EVAL_BATCH(FIXED, TG, NZ, BEST)                                      \
    {                                                                        \
        const u64 Bc = (FIXED) | base;                                       \
        u64 n1 = (Bc << 1) & M, n2 = (Bc >> 1) & M;                          \
        u64 n3 = Bc << 8, n4 = Bc >> 8;                                      \
        u64 n5 = n1 << 8, n6 = n1 >> 8, n7 = n2 << 8, n8 = n2 >> 8;          \
        u64 a1 = n1 ^ n2, b1 = n1 & n2;                                      \
        u64 a2 = n3 ^ n4, b2 = n3 & n4;                                      \
        u64 a3 = n5 ^ n6, b3 = n5 & n6;                                      \
        u64 a4 = n7 ^ n8, b4 = n7 & n8;                                      \
        u64 s1 = a1 ^ a2, t1 = a1 & a2;                                      \
        u64 s2 = a3 ^ a4, t2 = a3 & a4;                                      \
        u64 cc0 = s1 ^ s2, u0 = s1 & s2;                                     \
        u64 p1 = b1 ^ b2, q1 = b1 & b2;                                      \
        u64 p2 = b3 ^ b4, q2 = b3 & b4;                                      \
        u64 p3 = t1 ^ t2, q3 = t1 & t2;                                      \
        u64 r1 = p1 ^ p2, w1 = p1 & p2;                                      \
        u64 r2 = p3 ^ u0, w2 = p3 & u0;                                      \
        u64 cc1 = r1 ^ r2, w3 = r1 & r2;                                     \
        u64 hi = q1 | q2 | q3 | w1 | w2 | w3;                                \
        { /* j=0: no toggles */                                              \
            u64 nx = cc1 & ~hi & (cc0 | Bc);                                 \
            FIN(nx, TG, 4 * tid + 0, (NZ).x, BEST)                           \
        }                                                                    \
        { /* j=1: +bit36 */                                                  \
            u64 k0 = cc0 & M36, a0v = cc0 ^ M36;                             \
            u64 av = cc1 ^ k0, h = hi | (cc1 & k0);                          \
            u64 nx = av & ~h & (a0v | Bc | B36);                             \
            FIN(nx, TG, 4 * tid + 1, (NZ).y, BEST)                           \
        }                                                                    \
        { /* j=2: +bit35 */                                                  \
            u64 k0 = cc0 & M35, a0v = cc0 ^ M35;                             \
            u64 av = cc1 ^ k0, h = hi | (cc1 & k0);                          \
            u64 nx = av & ~h & (a0v | Bc | B35);                             \
            FIN(nx, TG, 4 * tid + 2, (NZ).z, BEST)                           \
        }                                                                    \
        { /* j=3: +bit35 then +bit36 (sequential ripple, exact) */           \
            u64 k0 = cc0 & M35, a0v = cc0 ^ M35;                             \
            u64 av = cc1 ^ k0, h1 = hi | (cc1 & k0);                         \
            u64 k1 = a0v & M36, g0 = a0v ^ M36;                              \
            u64 gv = av ^ k1, h2 = h1 | (av & k1);                           \
            u64 nx = gv & ~h2 & (g0 | Bc | B35 | B36);                       \
            FIN(nx, TG, 4 * tid + 3, (NZ).w, BEST)                           \
        }                                                                    \
    }

    EVAL_BATCH(fxA, tgA, nzA, bestA)
    EVAL_BATCH(fxB, tgB, nzB, bestB)
#undef EVAL_BATCH
#undef FIN

    // Warp argmin for both batches (packed keys, first-index tiebreak).
    #pragma unroll
    for (int s = 16; s; s >>= 1) {
        u64 oa = __shfl_xor_sync(0xffffffffu, bestA, s);
        u64 ob = __shfl_xor_sync(0xffffffffu, bestB, s);
        if (oa < bestA) bestA = oa;
        if (ob < bestB) bestB = ob;
    }
    if (lane == 0) { sk[0][warp] = bestA; sk[1][warp] = bestB; }

    __syncthreads();   // publishes sk; orders copy stores before patch

    if (tid < 9) {
        u64 k0 = sk[0][0];
        if (sk[0][1] < k0) k0 = sk[0][1];
        if (sk[0][2] < k0) k0 = sk[0][2];
        if (sk[0][3] < k0) k0 = sk[0][3];
        int best = (int)(unsigned)k0;
        float vv = ((best >> (8 - tid)) & 1) ? 1.0f : 0.0f;
        obA[(ry + tid / 3) * 25 + (rx + tid % 3)] = vv;
    } else if (warp == 1 && lane < 9) {
        u64 k0 = sk[1][0];
        if (sk[1][1] < k0) k0 = sk[1][1];
        if (sk[1][2] < k0) k0 = sk[1][2];
        if (sk[1][3] < k0) k0 = sk[1][3];
        int best = (int)(unsigned)k0;
        float vv = ((best >> (8 - lane)) & 1) ? 1.0f : 0.0f;
        obB[(ry + lane / 3) * 25 + (rx + lane % 3)] = vv;
    }
}

extern "C" void kernel_launch(void* const* d_in, const int* in_sizes, int n_in,
                              void* d_out, int out_size)
{
    const float* x      = (const float*)d_in[0];
    const float* target = (const float*)d_in[1];
    const float* noise  = (const float*)d_in[2];
    const int*   ryp    = (const int*)d_in[3];
    const int*   rxp    = (const int*)d_in[4];
    float* out = (float*)d_out;

    int B = in_sizes[0] / 625;
    bcl_kernel<<<(B + 1) / 2, 128>>>(x, target, noise, ryp, rxp, out, B);
}